// round 10
// baseline (speedup 1.0000x reference)
#include <cuda_runtime.h>
#include <cuda_fp16.h>
#include <cuda_bf16.h>

#define NN 100000
#define EE 3200000
#define IND 81
#define INDP 84
#define HID 64
#define LAT 32
#define BN_EPS 1e-5f
#define SCAN_BLK 1024

// Scratch (device globals; no allocation allowed)
__device__ __align__(128) __half2 g_half[NN * 32];   // fp16 Hs rows
__device__ float g_bufA[NN * HID];
__device__ float g_bufB[NN * HID];
__device__ float g_dis[NN];
__device__ int   g_cnt[NN];
__device__ int   g_rowptr[NN + 1];
__device__ int   g_cursor[NN + 1];
__device__ int   g_csr[EE];
__device__ int   g_bsums[(NN + SCAN_BLK - 1) / SCAN_BLK + 1];
__device__ float g_stats[256];   // [0:128) BN1 raw sums, [128:256) BN2 raw sums

// ---------------------------------------------------------------------------
__device__ __forceinline__ bool edges_are_i64(const void* ei) {
    long long v0 = ((const long long*)ei)[0];
    return (v0 >= 0 && v0 < 1000000LL);
}
__device__ __forceinline__ int edge_at(const void* ei, bool is64, int i) {
    return is64 ? (int)((const long long*)ei)[i] : ((const int*)ei)[i];
}

// ---------------------------------------------------------------------------
// Histogram of dst, 4 edges per thread (ILP=4).
__global__ void hist_dst(const void* ei, int* __restrict__ cnt, int E) {
    int t = blockIdx.x * blockDim.x + threadIdx.x;
    int base = t * 4;
    if (base >= E) return;
    bool is64 = edges_are_i64(ei);
    if (base + 4 <= E) {
        int d0, d1, d2, d3;
        if (is64) {
            const longlong2* p = (const longlong2*)((const long long*)ei + E);
            longlong2 a = __ldg(&p[t * 2]);
            longlong2 b = __ldg(&p[t * 2 + 1]);
            d0 = (int)a.x; d1 = (int)a.y; d2 = (int)b.x; d3 = (int)b.y;
        } else {
            const int4* p = (const int4*)((const int*)ei + E);
            int4 a = __ldg(&p[t]);
            d0 = a.x; d1 = a.y; d2 = a.z; d3 = a.w;
        }
        atomicAdd(&cnt[d0], 1);
        atomicAdd(&cnt[d1], 1);
        atomicAdd(&cnt[d2], 1);
        atomicAdd(&cnt[d3], 1);
    } else {
        for (int e = base; e < E; ++e)
            atomicAdd(&cnt[edge_at(ei, is64, E + e)], 1);
    }
}

// per-block inclusive scan of cnt -> rowptr[i+1] (block-local), raw block sums -> bsums
__global__ void scan1(const int* __restrict__ cnt, int* __restrict__ rowptr,
                      int* __restrict__ bsums, int n) {
    __shared__ int s[SCAN_BLK];
    int t = threadIdx.x;
    int i = blockIdx.x * SCAN_BLK + t;
    int val = (i < n) ? cnt[i] : 0;
    s[t] = val;
    __syncthreads();
    for (int off = 1; off < SCAN_BLK; off <<= 1) {
        int x = (t >= off) ? s[t - off] : 0;
        __syncthreads();
        s[t] += x;
        __syncthreads();
    }
    if (i < n) rowptr[i + 1] = s[t];
    if (t == SCAN_BLK - 1) bsums[blockIdx.x] = s[t];
}

// Add bsums prefix (inline per block), init cursor, dis = rsqrt(deg+1).
__global__ void scan3(int* __restrict__ rowptr, int* __restrict__ cursor,
                      const int* __restrict__ bsums, const int* __restrict__ cnt,
                      float* __restrict__ dis, int n, int nb) {
    __shared__ int pre[2];
    int t = threadIdx.x;
    int base = blockIdx.x * 256;
    int jmin = base / SCAN_BLK;
    int jmax = (base + 255) / SCAN_BLK;
    int wid = t >> 5, lane = t & 31;
    if (wid < 2) {
        int j = (wid == 0) ? jmin : jmax;
        int s = 0;
        for (int k = lane; k < j; k += 32) s += bsums[k];
        #pragma unroll
        for (int o = 16; o > 0; o >>= 1) s += __shfl_down_sync(0xffffffffu, s, o);
        if (lane == 0) pre[wid] = s;
    }
    __syncthreads();
    int i = base + t;
    if (i == 0) { rowptr[0] = 0; cursor[0] = 0; }
    if (i < n) {
        int myj = i / SCAN_BLK;
        int off = (myj == jmin) ? pre[0] : pre[1];
        int v = rowptr[i + 1] + off;
        rowptr[i + 1] = v;
        cursor[i + 1] = v;
        dis[i] = rsqrtf((float)(cnt[i] + 1));
    }
}

// Scatter edges into CSR, 4 edges per thread (ILP=4, independent atomic chains).
__global__ void scatter_csr(const void* ei, int* __restrict__ cursor,
                            int* __restrict__ csr, int E) {
    int t = blockIdx.x * blockDim.x + threadIdx.x;
    int base = t * 4;
    if (base >= E) return;
    bool is64 = edges_are_i64(ei);
    if (base + 4 <= E) {
        int s0, s1, s2, s3, d0, d1, d2, d3;
        if (is64) {
            const longlong2* ps = (const longlong2*)ei;
            const longlong2* pd = (const longlong2*)((const long long*)ei + E);
            longlong2 sa = __ldg(&ps[t * 2]);
            longlong2 sb = __ldg(&ps[t * 2 + 1]);
            longlong2 da = __ldg(&pd[t * 2]);
            longlong2 db = __ldg(&pd[t * 2 + 1]);
            s0 = (int)sa.x; s1 = (int)sa.y; s2 = (int)sb.x; s3 = (int)sb.y;
            d0 = (int)da.x; d1 = (int)da.y; d2 = (int)db.x; d3 = (int)db.y;
        } else {
            const int4* ps = (const int4*)ei;
            const int4* pd = (const int4*)((const int*)ei + E);
            int4 sa = __ldg(&ps[t]);
            int4 da = __ldg(&pd[t]);
            s0 = sa.x; s1 = sa.y; s2 = sa.z; s3 = sa.w;
            d0 = da.x; d1 = da.y; d2 = da.z; d3 = da.w;
        }
        int p0 = atomicAdd(&cursor[d0], 1);
        int p1 = atomicAdd(&cursor[d1], 1);
        int p2 = atomicAdd(&cursor[d2], 1);
        int p3 = atomicAdd(&cursor[d3], 1);
        csr[p0] = s0;
        csr[p1] = s1;
        csr[p2] = s2;
        csr[p3] = s3;
    } else {
        for (int e = base; e < E; ++e) {
            int s = edge_at(ei, is64, e);
            int d = edge_at(ei, is64, E + e);
            int pos = atomicAdd(&cursor[d], 1);
            csr[pos] = s;
        }
    }
}

// ---------------------------------------------------------------------------
// GEMM: Yh[N,64] = half((X[N,81] @ W[81,64]) * dis[n])
__global__ void gemm81_dis(const float* __restrict__ X, const float* __restrict__ W,
                           const float* __restrict__ dis, __half* __restrict__ Yh, int N) {
    __shared__ float Ws[IND * HID];
    __shared__ __align__(16) float Xs[16][INDP];
    int tx = threadIdx.x;
    int ty = threadIdx.y;
    int tid = ty * 64 + tx;
    for (int i = tid; i < IND * HID; i += 256) Ws[i] = W[i];
    int n0 = blockIdx.x * 16;
    for (int i = tid; i < 16 * IND; i += 256) {
        int r = i / IND, c = i % IND;
        int n = n0 + r;
        Xs[r][c] = (n < N) ? X[n * IND + c] : 0.0f;
    }
    __syncthreads();
    float acc[4] = {0.f, 0.f, 0.f, 0.f};
    #pragma unroll 5
    for (int k = 0; k < 80; k += 4) {
        float w0 = Ws[(k + 0) * HID + tx];
        float w1 = Ws[(k + 1) * HID + tx];
        float w2 = Ws[(k + 2) * HID + tx];
        float w3 = Ws[(k + 3) * HID + tx];
        #pragma unroll
        for (int r = 0; r < 4; ++r) {
            float4 xv = *reinterpret_cast<const float4*>(&Xs[ty * 4 + r][k]);
            acc[r] += xv.x * w0 + xv.y * w1 + xv.z * w2 + xv.w * w3;
        }
    }
    {
        float w = Ws[80 * HID + tx];
        #pragma unroll
        for (int r = 0; r < 4; ++r) acc[r] += Xs[ty * 4 + r][80] * w;
    }
    #pragma unroll
    for (int r = 0; r < 4; ++r) {
        int n = n0 + ty * 4 + r;
        if (n < N) Yh[n * HID + tx] = __float2half(acc[r] * __ldg(&dis[n]));
    }
}

// GEMM with fused BN-finalize + BN-apply + ReLU input transform.
__global__ void gemm64_bn_dis(const float* __restrict__ X, const float* __restrict__ W,
                              const float* __restrict__ rawstats,
                              const float* __restrict__ g, const float* __restrict__ beta,
                              const float* __restrict__ dis,
                              __half* __restrict__ Yh, int N) {
    __shared__ float Ws[HID * HID];
    __shared__ __align__(16) float Xs[16][HID];
    __shared__ float sc[64], sh[64];
    int tx = threadIdx.x;
    int ty = threadIdx.y;
    int tid = ty * 64 + tx;
    for (int i = tid; i < HID * HID; i += 256) Ws[i] = W[i];
    if (tid < 64) {
        float invN = 1.0f / (float)N;
        float m = rawstats[tid] * invN;
        float v = rawstats[64 + tid] * invN - m * m;
        float scale = g[tid] * rsqrtf(v + BN_EPS);
        sc[tid] = scale;
        sh[tid] = beta[tid] - m * scale;
    }
    int n0 = blockIdx.x * 16;
    __syncthreads();
    for (int i = tid; i < 16 * HID; i += 256) {
        int r = i >> 6, c = i & 63;
        int n = n0 + r;
        float raw = (n < N) ? X[n * HID + c] : 0.0f;
        Xs[r][c] = fmaxf(fmaf(raw, sc[c], sh[c]), 0.0f);
    }
    __syncthreads();
    float acc[4] = {0.f, 0.f, 0.f, 0.f};
    #pragma unroll 4
    for (int k = 0; k < HID; k += 4) {
        float w0 = Ws[(k + 0) * HID + tx];
        float w1 = Ws[(k + 1) * HID + tx];
        float w2 = Ws[(k + 2) * HID + tx];
        float w3 = Ws[(k + 3) * HID + tx];
        #pragma unroll
        for (int r = 0; r < 4; ++r) {
            float4 xv = *reinterpret_cast<const float4*>(&Xs[ty * 4 + r][k]);
            acc[r] += xv.x * w0 + xv.y * w1 + xv.z * w2 + xv.w * w3;
        }
    }
    #pragma unroll
    for (int r = 0; r < 4; ++r) {
        int n = n0 + ty * 4 + r;
        if (n < N) Yh[n * HID + tx] = __float2half(acc[r] * __ldg(&dis[n]));
    }
}

// Final heads
__global__ void gemm_mu_ls(const float* __restrict__ X,
                           const float* __restrict__ Wmu, const float* __restrict__ bmu,
                           const float* __restrict__ Wls, const float* __restrict__ bls,
                           float* __restrict__ out, int N) {
    __shared__ float Ws[HID * 64];
    __shared__ float bs[64];
    __shared__ __align__(16) float Xs[16][HID];
    int tx = threadIdx.x;
    int ty = threadIdx.y;
    int tid = ty * 64 + tx;
    for (int i = tid; i < HID * 64; i += 256) {
        int k = i >> 6, f = i & 63;
        Ws[i] = (f < LAT) ? Wmu[k * LAT + f] : Wls[k * LAT + (f - LAT)];
    }
    if (tid < 64) bs[tid] = (tid < LAT) ? bmu[tid] : bls[tid - LAT];
    int n0 = blockIdx.x * 16;
    for (int i = tid; i < 16 * HID; i += 256) {
        int r = i >> 6, c = i & 63;
        int n = n0 + r;
        Xs[r][c] = (n < N) ? X[n * HID + c] : 0.0f;
    }
    __syncthreads();
    float acc[4] = {0.f, 0.f, 0.f, 0.f};
    #pragma unroll 4
    for (int k = 0; k < HID; k += 4) {
        float w0 = Ws[(k + 0) * 64 + tx];
        float w1 = Ws[(k + 1) * 64 + tx];
        float w2 = Ws[(k + 2) * 64 + tx];
        float w3 = Ws[(k + 3) * 64 + tx];
        #pragma unroll
        for (int r = 0; r < 4; ++r) {
            float4 xv = *reinterpret_cast<const float4*>(&Xs[ty * 4 + r][k]);
            acc[r] += xv.x * w0 + xv.y * w1 + xv.z * w2 + xv.w * w3;
        }
    }
    int f = tx & (LAT - 1);
    long long off = (tx < LAT) ? 0 : (long long)N * LAT;
    #pragma unroll
    for (int r = 0; r < 4; ++r) {
        int n = n0 + ty * 4 + r;
        if (n < N) out[off + (long long)n * LAT + f] = acc[r] + bs[tx];
    }
}

// ---------------------------------------------------------------------------
// Aggregation, 2 nodes per warp (unchanged)
__global__ void aggregate_h2(const __half2* __restrict__ Hh, const int* __restrict__ rowptr,
                             const int* __restrict__ csr, const float* __restrict__ dis,
                             const float* __restrict__ bias, float4* __restrict__ out4, int N) {
    int warp = (blockIdx.x * blockDim.x + threadIdx.x) >> 5;
    int lane = threadIdx.x & 31;
    int grp = lane >> 4;
    int sub = lane & 15;
    int n = warp * 2 + grp;
    if (n >= N) return;

    const uint2* Hr = (const uint2*)Hh;
    uint2 raw = __ldg(&Hr[n * 16 + sub]);
    __half2 h0 = *reinterpret_cast<__half2*>(&raw.x);
    __half2 h1 = *reinterpret_cast<__half2*>(&raw.y);
    float2 p0 = __half22float2(h0), p1 = __half22float2(h1);
    float ax0 = p0.x, ay0 = p0.y, az0 = p1.x, aw0 = p1.y;
    float ax1 = 0.f, ay1 = 0.f, az1 = 0.f, aw1 = 0.f;

    int j = __ldg(&rowptr[n]);
    int end = __ldg(&rowptr[n + 1]);
    for (; j + 2 <= end; j += 2) {
        int s0 = __ldg(&csr[j]);
        int s1 = __ldg(&csr[j + 1]);
        uint2 r0 = __ldg(&Hr[s0 * 16 + sub]);
        uint2 r1 = __ldg(&Hr[s1 * 16 + sub]);
        float2 v00 = __half22float2(*reinterpret_cast<__half2*>(&r0.x));
        float2 v01 = __half22float2(*reinterpret_cast<__half2*>(&r0.y));
        float2 v10 = __half22float2(*reinterpret_cast<__half2*>(&r1.x));
        float2 v11 = __half22float2(*reinterpret_cast<__half2*>(&r1.y));
        ax0 += v00.x; ay0 += v00.y; az0 += v01.x; aw0 += v01.y;
        ax1 += v10.x; ay1 += v10.y; az1 += v11.x; aw1 += v11.y;
    }
    if (j < end) {
        int s0 = __ldg(&csr[j]);
        uint2 r0 = __ldg(&Hr[s0 * 16 + sub]);
        float2 v00 = __half22float2(*reinterpret_cast<__half2*>(&r0.x));
        float2 v01 = __half22float2(*reinterpret_cast<__half2*>(&r0.y));
        ax0 += v00.x; ay0 += v00.y; az0 += v01.x; aw0 += v01.y;
    }

    float dd = __ldg(&dis[n]);
    float4 bb = make_float4(0.f, 0.f, 0.f, 0.f);
    if (bias) bb = ((const float4*)bias)[sub];
    out4[n * 16 + sub] = make_float4(fmaf(ax0 + ax1, dd, bb.x),
                                     fmaf(ay0 + ay1, dd, bb.y),
                                     fmaf(az0 + az1, dd, bb.z),
                                     fmaf(aw0 + aw1, dd, bb.w));
}

// ---------------------------------------------------------------------------
// BN stats: raw sum/sumsq accumulated via atomics (buffer pre-zeroed by memset).
__global__ void bn_stats(const float* __restrict__ H, float* stats, int N) {
    int tid = threadIdx.x;
    int col = tid & 63;
    int r = blockIdx.x * 4 + (tid >> 6);
    int rstride = gridDim.x * 4;
    float s = 0.0f, q = 0.0f;
    for (; r < N; r += rstride) {
        float v = H[r * HID + col];
        s += v; q += v * v;
    }
    __shared__ float sh[256], qh[256];
    sh[tid] = s; qh[tid] = q;
    __syncthreads();
    if (tid < 64) {
        float S = sh[tid] + sh[tid + 64] + sh[tid + 128] + sh[tid + 192];
        float Q = qh[tid] + qh[tid + 64] + qh[tid + 128] + qh[tid + 192];
        atomicAdd(&stats[tid], S);
        atomicAdd(&stats[64 + tid], Q);
    }
}

// Hs[n,f] = half(relu(bn(B[n,f])) * dis[n]) — BN finalize in-block from raw sums.
__global__ void bn_relu_dis(const float* __restrict__ H, const float* __restrict__ rawstats,
                            const float* __restrict__ g, const float* __restrict__ beta,
                            const float* __restrict__ dis, __half* __restrict__ out,
                            int total, int N) {
    __shared__ float sc[64], sh[64];
    int t = threadIdx.x;
    if (t < 64) {
        float invN = 1.0f / (float)N;
        float m = rawstats[t] * invN;
        float v = rawstats[64 + t] * invN - m * m;
        float scale = g[t] * rsqrtf(v + BN_EPS);
        sc[t] = scale;
        sh[t] = beta[t] - m * scale;
    }
    __syncthreads();
    int idx = blockIdx.x * blockDim.x + t;
    if (idx >= total) return;
    int f = idx & 63;
    int n = idx >> 6;
    float y = fmaxf(fmaf(H[idx], sc[f], sh[f]), 0.0f);
    out[idx] = __float2half(y * __ldg(&dis[n]));
}

// ---------------------------------------------------------------------------
extern "C" void kernel_launch(void* const* d_in, const int* in_sizes, int n_in,
                              void* d_out, int out_size) {
    const float* x    = (const float*)d_in[0];
    const void*  ei   = d_in[1];
    const float* W1   = (const float*)d_in[2];
    const float* b1   = (const float*)d_in[3];
    const float* g1   = (const float*)d_in[4];
    const float* be1  = (const float*)d_in[5];
    const float* W2   = (const float*)d_in[6];
    const float* b2   = (const float*)d_in[7];
    const float* g2   = (const float*)d_in[8];
    const float* be2  = (const float*)d_in[9];
    const float* Wmu  = (const float*)d_in[10];
    const float* bmu  = (const float*)d_in[11];
    const float* Wls  = (const float*)d_in[12];
    const float* bls  = (const float*)d_in[13];
    float* out = (float*)d_out;

    int N = in_sizes[0] / IND;
    int E = in_sizes[1] / 2;

    float *pA, *pB, *pDis, *pStats;
    __half2* pH;
    int *pCnt, *pRow, *pCur, *pCsr, *pBs;
    cudaGetSymbolAddress((void**)&pA, g_bufA);
    cudaGetSymbolAddress((void**)&pB, g_bufB);
    cudaGetSymbolAddress((void**)&pDis, g_dis);
    cudaGetSymbolAddress((void**)&pStats, g_stats);
    cudaGetSymbolAddress((void**)&pH, g_half);
    cudaGetSymbolAddress((void**)&pCnt, g_cnt);
    cudaGetSymbolAddress((void**)&pRow, g_rowptr);
    cudaGetSymbolAddress((void**)&pCur, g_cursor);
    cudaGetSymbolAddress((void**)&pCsr, g_csr);
    cudaGetSymbolAddress((void**)&pBs, g_bsums);

    float* pStats1 = pStats;
    float* pStats2 = pStats + 128;

    int NH = N * HID;
    int nScanBlocks = (N + SCAN_BLK - 1) / SCAN_BLK;
    dim3 gThr(64, 4);
    int gemmGrid = (N + 15) / 16;
    int aggGrid = ((N + 1) / 2 * 32 + 255) / 256;
    int edge4Grid = ((E + 3) / 4 + 255) / 256;    // 4 edges per thread

    // 0. zeroing via memset nodes
    cudaMemsetAsync(pCnt, 0, (size_t)N * sizeof(int));
    cudaMemsetAsync(pStats, 0, 256 * sizeof(float));

    // 1. CSR build + normalization (ILP=4 edge passes)
    hist_dst<<<edge4Grid, 256>>>(ei, pCnt, E);
    scan1<<<nScanBlocks, SCAN_BLK>>>(pCnt, pRow, pBs, N);
    scan3<<<(N + 255) / 256, 256>>>(pRow, pCur, pBs, pCnt, pDis, N, nScanBlocks);
    scatter_csr<<<edge4Grid, 256>>>(ei, pCur, pCsr, E);

    // 2. conv1
    gemm81_dis<<<gemmGrid, gThr>>>(x, W1, pDis, (__half*)pH, N);
    aggregate_h2<<<aggGrid, 256>>>(pH, pRow, pCsr, pDis, b1, (float4*)pB, N);

    // 3. BN1 raw stats
    bn_stats<<<512, 256>>>(pB, pStats1, N);

    // 4. conv2
    gemm64_bn_dis<<<gemmGrid, gThr>>>(pB, W2, pStats1, g1, be1, pDis, (__half*)pH, N);
    aggregate_h2<<<aggGrid, 256>>>(pH, pRow, pCsr, pDis, b2, (float4*)pA, N);

    // 5. BN2 raw stats
    bn_stats<<<512, 256>>>(pA, pStats2, N);

    // 6. Hs = relu(bn(A)) * dis ; shared aggregation for both heads
    bn_relu_dis<<<(NH + 255) / 256, 256>>>(pA, pStats2, g2, be2, pDis, (__half*)pH, NH, N);
    aggregate_h2<<<aggGrid, 256>>>(pH, pRow, pCsr, pDis, (const float*)nullptr, (float4*)pB, N);

    // 7. heads
    gemm_mu_ls<<<gemmGrid, gThr>>>(pB, Wmu, bmu, Wls, bls, out, N);
}

// round 11
// speedup vs baseline: 1.0110x; 1.0110x over previous
#include <cuda_runtime.h>
#include <cuda_fp16.h>
#include <cuda_bf16.h>

#define NN 100000
#define EE 3200000
#define IND 81
#define INDP 84
#define HID 64
#define LAT 32
#define BN_EPS 1e-5f
#define SCAN_BLK 1024

// Scratch (device globals; no allocation allowed)
__device__ __align__(128) __half2 g_half[NN * 32];   // fp16 Hs rows
__device__ float g_bufA[NN * HID];
__device__ float g_bufB[NN * HID];
__device__ float g_dis[NN];
__device__ int   g_cnt[NN];
__device__ int   g_rowptr[NN + 1];
__device__ int   g_cursor[NN + 1];
__device__ int   g_csr[EE];
__device__ int   g_bsums[(NN + SCAN_BLK - 1) / SCAN_BLK + 1];
__device__ float g_stats[256];   // [0:128) BN1 raw sums, [128:256) BN2 raw sums

// ---------------------------------------------------------------------------
__device__ __forceinline__ bool edges_are_i64(const void* ei) {
    long long v0 = ((const long long*)ei)[0];
    return (v0 >= 0 && v0 < 1000000LL);
}
__device__ __forceinline__ int edge_at(const void* ei, bool is64, int i) {
    return is64 ? (int)((const long long*)ei)[i] : ((const int*)ei)[i];
}

// ---------------------------------------------------------------------------
__global__ void hist_dst(const void* ei, int* cnt, int E) {
    int e = blockIdx.x * blockDim.x + threadIdx.x;
    if (e >= E) return;
    bool is64 = edges_are_i64(ei);
    int d = edge_at(ei, is64, E + e);
    atomicAdd(&cnt[d], 1);
}

__global__ void scan1(const int* __restrict__ cnt, int* __restrict__ rowptr,
                      int* __restrict__ bsums, int n) {
    __shared__ int s[SCAN_BLK];
    int t = threadIdx.x;
    int i = blockIdx.x * SCAN_BLK + t;
    int val = (i < n) ? cnt[i] : 0;
    s[t] = val;
    __syncthreads();
    for (int off = 1; off < SCAN_BLK; off <<= 1) {
        int x = (t >= off) ? s[t - off] : 0;
        __syncthreads();
        s[t] += x;
        __syncthreads();
    }
    if (i < n) rowptr[i + 1] = s[t];
    if (t == SCAN_BLK - 1) bsums[blockIdx.x] = s[t];
}

__global__ void scan3(int* __restrict__ rowptr, int* __restrict__ cursor,
                      const int* __restrict__ bsums, const int* __restrict__ cnt,
                      float* __restrict__ dis, int n, int nb) {
    __shared__ int pre[2];
    int t = threadIdx.x;
    int base = blockIdx.x * 256;
    int jmin = base / SCAN_BLK;
    int jmax = (base + 255) / SCAN_BLK;
    int wid = t >> 5, lane = t & 31;
    if (wid < 2) {
        int j = (wid == 0) ? jmin : jmax;
        int s = 0;
        for (int k = lane; k < j; k += 32) s += bsums[k];
        #pragma unroll
        for (int o = 16; o > 0; o >>= 1) s += __shfl_down_sync(0xffffffffu, s, o);
        if (lane == 0) pre[wid] = s;
    }
    __syncthreads();
    int i = base + t;
    if (i == 0) { rowptr[0] = 0; cursor[0] = 0; }
    if (i < n) {
        int myj = i / SCAN_BLK;
        int off = (myj == jmin) ? pre[0] : pre[1];
        int v = rowptr[i + 1] + off;
        rowptr[i + 1] = v;
        cursor[i + 1] = v;
        dis[i] = rsqrtf((float)(cnt[i] + 1));
    }
}

__global__ void scatter_csr(const void* ei, int* __restrict__ cursor,
                            int* __restrict__ csr, int E) {
    int e = blockIdx.x * blockDim.x + threadIdx.x;
    if (e >= E) return;
    bool is64 = edges_are_i64(ei);
    int s = edge_at(ei, is64, e);
    int d = edge_at(ei, is64, E + e);
    int pos = atomicAdd(&cursor[d], 1);
    csr[pos] = s;
}

// ---------------------------------------------------------------------------
// GEMM: Yh[N,64] = half(X[N,81] @ W[81,64])    (NO dis scale — applied later)
__global__ void gemm81_h(const float* __restrict__ X, const float* __restrict__ W,
                         __half* __restrict__ Yh, int N) {
    __shared__ float Ws[IND * HID];
    __shared__ __align__(16) float Xs[16][INDP];
    int tx = threadIdx.x;
    int ty = threadIdx.y;
    int tid = ty * 64 + tx;
    for (int i = tid; i < IND * HID; i += 256) Ws[i] = W[i];
    int n0 = blockIdx.x * 16;
    for (int i = tid; i < 16 * IND; i += 256) {
        int r = i / IND, c = i % IND;
        int n = n0 + r;
        Xs[r][c] = (n < N) ? X[n * IND + c] : 0.0f;
    }
    __syncthreads();
    float acc[4] = {0.f, 0.f, 0.f, 0.f};
    #pragma unroll 5
    for (int k = 0; k < 80; k += 4) {
        float w0 = Ws[(k + 0) * HID + tx];
        float w1 = Ws[(k + 1) * HID + tx];
        float w2 = Ws[(k + 2) * HID + tx];
        float w3 = Ws[(k + 3) * HID + tx];
        #pragma unroll
        for (int r = 0; r < 4; ++r) {
            float4 xv = *reinterpret_cast<const float4*>(&Xs[ty * 4 + r][k]);
            acc[r] += xv.x * w0 + xv.y * w1 + xv.z * w2 + xv.w * w3;
        }
    }
    {
        float w = Ws[80 * HID + tx];
        #pragma unroll
        for (int r = 0; r < 4; ++r) acc[r] += Xs[ty * 4 + r][80] * w;
    }
    #pragma unroll
    for (int r = 0; r < 4; ++r) {
        int n = n0 + ty * 4 + r;
        if (n < N) Yh[n * HID + tx] = __float2half(acc[r]);
    }
}

// In-place row scale: Hh[n,:] *= dis[n]   (fp16)
__global__ void scale_dis(__half2* __restrict__ H, const float* __restrict__ dis, int total2) {
    int idx = blockIdx.x * blockDim.x + threadIdx.x;
    if (idx >= total2) return;
    int n = idx >> 5;
    float d = __ldg(&dis[n]);
    float2 v = __half22float2(H[idx]);
    H[idx] = __floats2half2_rn(v.x * d, v.y * d);
}

// GEMM with fused BN-finalize + BN-apply + ReLU input transform.
__global__ void gemm64_bn_dis(const float* __restrict__ X, const float* __restrict__ W,
                              const float* __restrict__ rawstats,
                              const float* __restrict__ g, const float* __restrict__ beta,
                              const float* __restrict__ dis,
                              __half* __restrict__ Yh, int N) {
    __shared__ float Ws[HID * HID];
    __shared__ __align__(16) float Xs[16][HID];
    __shared__ float sc[64], sh[64];
    int tx = threadIdx.x;
    int ty = threadIdx.y;
    int tid = ty * 64 + tx;
    for (int i = tid; i < HID * HID; i += 256) Ws[i] = W[i];
    if (tid < 64) {
        float invN = 1.0f / (float)N;
        float m = rawstats[tid] * invN;
        float v = rawstats[64 + tid] * invN - m * m;
        float scale = g[tid] * rsqrtf(v + BN_EPS);
        sc[tid] = scale;
        sh[tid] = beta[tid] - m * scale;
    }
    int n0 = blockIdx.x * 16;
    __syncthreads();
    for (int i = tid; i < 16 * HID; i += 256) {
        int r = i >> 6, c = i & 63;
        int n = n0 + r;
        float raw = (n < N) ? X[n * HID + c] : 0.0f;
        Xs[r][c] = fmaxf(fmaf(raw, sc[c], sh[c]), 0.0f);
    }
    __syncthreads();
    float acc[4] = {0.f, 0.f, 0.f, 0.f};
    #pragma unroll 4
    for (int k = 0; k < HID; k += 4) {
        float w0 = Ws[(k + 0) * HID + tx];
        float w1 = Ws[(k + 1) * HID + tx];
        float w2 = Ws[(k + 2) * HID + tx];
        float w3 = Ws[(k + 3) * HID + tx];
        #pragma unroll
        for (int r = 0; r < 4; ++r) {
            float4 xv = *reinterpret_cast<const float4*>(&Xs[ty * 4 + r][k]);
            acc[r] += xv.x * w0 + xv.y * w1 + xv.z * w2 + xv.w * w3;
        }
    }
    #pragma unroll
    for (int r = 0; r < 4; ++r) {
        int n = n0 + ty * 4 + r;
        if (n < N) Yh[n * HID + tx] = __float2half(acc[r] * __ldg(&dis[n]));
    }
}

// Final heads
__global__ void gemm_mu_ls(const float* __restrict__ X,
                           const float* __restrict__ Wmu, const float* __restrict__ bmu,
                           const float* __restrict__ Wls, const float* __restrict__ bls,
                           float* __restrict__ out, int N) {
    __shared__ float Ws[HID * 64];
    __shared__ float bs[64];
    __shared__ __align__(16) float Xs[16][HID];
    int tx = threadIdx.x;
    int ty = threadIdx.y;
    int tid = ty * 64 + tx;
    for (int i = tid; i < HID * 64; i += 256) {
        int k = i >> 6, f = i & 63;
        Ws[i] = (f < LAT) ? Wmu[k * LAT + f] : Wls[k * LAT + (f - LAT)];
    }
    if (tid < 64) bs[tid] = (tid < LAT) ? bmu[tid] : bls[tid - LAT];
    int n0 = blockIdx.x * 16;
    for (int i = tid; i < 16 * HID; i += 256) {
        int r = i >> 6, c = i & 63;
        int n = n0 + r;
        Xs[r][c] = (n < N) ? X[n * HID + c] : 0.0f;
    }
    __syncthreads();
    float acc[4] = {0.f, 0.f, 0.f, 0.f};
    #pragma unroll 4
    for (int k = 0; k < HID; k += 4) {
        float w0 = Ws[(k + 0) * 64 + tx];
        float w1 = Ws[(k + 1) * 64 + tx];
        float w2 = Ws[(k + 2) * 64 + tx];
        float w3 = Ws[(k + 3) * 64 + tx];
        #pragma unroll
        for (int r = 0; r < 4; ++r) {
            float4 xv = *reinterpret_cast<const float4*>(&Xs[ty * 4 + r][k]);
            acc[r] += xv.x * w0 + xv.y * w1 + xv.z * w2 + xv.w * w3;
        }
    }
    int f = tx & (LAT - 1);
    long long off = (tx < LAT) ? 0 : (long long)N * LAT;
    #pragma unroll
    for (int r = 0; r < 4; ++r) {
        int n = n0 + ty * 4 + r;
        if (n < N) out[off + (long long)n * LAT + f] = acc[r] + bs[tx];
    }
}

// ---------------------------------------------------------------------------
// Aggregation, 2 nodes per warp (unchanged)
__global__ void aggregate_h2(const __half2* __restrict__ Hh, const int* __restrict__ rowptr,
                             const int* __restrict__ csr, const float* __restrict__ dis,
                             const float* __restrict__ bias, float4* __restrict__ out4, int N) {
    int warp = (blockIdx.x * blockDim.x + threadIdx.x) >> 5;
    int lane = threadIdx.x & 31;
    int grp = lane >> 4;
    int sub = lane & 15;
    int n = warp * 2 + grp;
    if (n >= N) return;

    const uint2* Hr = (const uint2*)Hh;
    uint2 raw = __ldg(&Hr[n * 16 + sub]);
    __half2 h0 = *reinterpret_cast<__half2*>(&raw.x);
    __half2 h1 = *reinterpret_cast<__half2*>(&raw.y);
    float2 p0 = __half22float2(h0), p1 = __half22float2(h1);
    float ax0 = p0.x, ay0 = p0.y, az0 = p1.x, aw0 = p1.y;
    float ax1 = 0.f, ay1 = 0.f, az1 = 0.f, aw1 = 0.f;

    int j = __ldg(&rowptr[n]);
    int end = __ldg(&rowptr[n + 1]);
    for (; j + 2 <= end; j += 2) {
        int s0 = __ldg(&csr[j]);
        int s1 = __ldg(&csr[j + 1]);
        uint2 r0 = __ldg(&Hr[s0 * 16 + sub]);
        uint2 r1 = __ldg(&Hr[s1 * 16 + sub]);
        float2 v00 = __half22float2(*reinterpret_cast<__half2*>(&r0.x));
        float2 v01 = __half22float2(*reinterpret_cast<__half2*>(&r0.y));
        float2 v10 = __half22float2(*reinterpret_cast<__half2*>(&r1.x));
        float2 v11 = __half22float2(*reinterpret_cast<__half2*>(&r1.y));
        ax0 += v00.x; ay0 += v00.y; az0 += v01.x; aw0 += v01.y;
        ax1 += v10.x; ay1 += v10.y; az1 += v11.x; aw1 += v11.y;
    }
    if (j < end) {
        int s0 = __ldg(&csr[j]);
        uint2 r0 = __ldg(&Hr[s0 * 16 + sub]);
        float2 v00 = __half22float2(*reinterpret_cast<__half2*>(&r0.x));
        float2 v01 = __half22float2(*reinterpret_cast<__half2*>(&r0.y));
        ax0 += v00.x; ay0 += v00.y; az0 += v01.x; aw0 += v01.y;
    }

    float dd = __ldg(&dis[n]);
    float4 bb = make_float4(0.f, 0.f, 0.f, 0.f);
    if (bias) bb = ((const float4*)bias)[sub];
    out4[n * 16 + sub] = make_float4(fmaf(ax0 + ax1, dd, bb.x),
                                     fmaf(ay0 + ay1, dd, bb.y),
                                     fmaf(az0 + az1, dd, bb.z),
                                     fmaf(aw0 + aw1, dd, bb.w));
}

// ---------------------------------------------------------------------------
// BN stats: raw sum/sumsq accumulated via atomics (buffer pre-zeroed by memset).
__global__ void bn_stats(const float* __restrict__ H, float* stats, int N) {
    int tid = threadIdx.x;
    int col = tid & 63;
    int r = blockIdx.x * 4 + (tid >> 6);
    int rstride = gridDim.x * 4;
    float s = 0.0f, q = 0.0f;
    for (; r < N; r += rstride) {
        float v = H[r * HID + col];
        s += v; q += v * v;
    }
    __shared__ float sh[256], qh[256];
    sh[tid] = s; qh[tid] = q;
    __syncthreads();
    if (tid < 64) {
        float S = sh[tid] + sh[tid + 64] + sh[tid + 128] + sh[tid + 192];
        float Q = qh[tid] + qh[tid + 64] + qh[tid + 128] + qh[tid + 192];
        atomicAdd(&stats[tid], S);
        atomicAdd(&stats[64 + tid], Q);
    }
}

// Hs[n,f] = half(relu(bn(B[n,f])) * dis[n]) — BN finalize in-block from raw sums.
__global__ void bn_relu_dis(const float* __restrict__ H, const float* __restrict__ rawstats,
                            const float* __restrict__ g, const float* __restrict__ beta,
                            const float* __restrict__ dis, __half* __restrict__ out,
                            int total, int N) {
    __shared__ float sc[64], sh[64];
    int t = threadIdx.x;
    if (t < 64) {
        float invN = 1.0f / (float)N;
        float m = rawstats[t] * invN;
        float v = rawstats[64 + t] * invN - m * m;
        float scale = g[t] * rsqrtf(v + BN_EPS);
        sc[t] = scale;
        sh[t] = beta[t] - m * scale;
    }
    __syncthreads();
    int idx = blockIdx.x * blockDim.x + t;
    if (idx >= total) return;
    int f = idx & 63;
    int n = idx >> 6;
    float y = fmaxf(fmaf(H[idx], sc[f], sh[f]), 0.0f);
    out[idx] = __float2half(y * __ldg(&dis[n]));
}

// ---------------------------------------------------------------------------
extern "C" void kernel_launch(void* const* d_in, const int* in_sizes, int n_in,
                              void* d_out, int out_size) {
    const float* x    = (const float*)d_in[0];
    const void*  ei   = d_in[1];
    const float* W1   = (const float*)d_in[2];
    const float* b1   = (const float*)d_in[3];
    const float* g1   = (const float*)d_in[4];
    const float* be1  = (const float*)d_in[5];
    const float* W2   = (const float*)d_in[6];
    const float* b2   = (const float*)d_in[7];
    const float* g2   = (const float*)d_in[8];
    const float* be2  = (const float*)d_in[9];
    const float* Wmu  = (const float*)d_in[10];
    const float* bmu  = (const float*)d_in[11];
    const float* Wls  = (const float*)d_in[12];
    const float* bls  = (const float*)d_in[13];
    float* out = (float*)d_out;

    int N = in_sizes[0] / IND;
    int E = in_sizes[1] / 2;

    float *pA, *pB, *pDis, *pStats;
    __half2* pH;
    int *pCnt, *pRow, *pCur, *pCsr, *pBs;
    cudaGetSymbolAddress((void**)&pA, g_bufA);
    cudaGetSymbolAddress((void**)&pB, g_bufB);
    cudaGetSymbolAddress((void**)&pDis, g_dis);
    cudaGetSymbolAddress((void**)&pStats, g_stats);
    cudaGetSymbolAddress((void**)&pH, g_half);
    cudaGetSymbolAddress((void**)&pCnt, g_cnt);
    cudaGetSymbolAddress((void**)&pRow, g_rowptr);
    cudaGetSymbolAddress((void**)&pCur, g_cursor);
    cudaGetSymbolAddress((void**)&pCsr, g_csr);
    cudaGetSymbolAddress((void**)&pBs, g_bsums);

    float* pStats1 = pStats;
    float* pStats2 = pStats + 128;

    int NH = N * HID;
    int total2 = N * 32;
    int nScanBlocks = (N + SCAN_BLK - 1) / SCAN_BLK;
    dim3 gThr(64, 4);
    int gemmGrid = (N + 15) / 16;
    int aggGrid = ((N + 1) / 2 * 32 + 255) / 256;

    // Side stream + events, created once on the (uncaptured) first call.
    static cudaStream_t s2 = nullptr;
    static cudaEvent_t evFork = nullptr, evDis = nullptr, evJoin = nullptr;
    if (!s2) {
        cudaStreamCreateWithFlags(&s2, cudaStreamNonBlocking);
        cudaEventCreateWithFlags(&evFork, cudaEventDisableTiming);
        cudaEventCreateWithFlags(&evDis, cudaEventDisableTiming);
        cudaEventCreateWithFlags(&evJoin, cudaEventDisableTiming);
    }

    // 0. zeroing (stream 0)
    cudaMemsetAsync(pCnt, 0, (size_t)N * sizeof(int));
    cudaMemsetAsync(pStats, 0, 256 * sizeof(float));

    // Fork: gemm81 (no dis) on s2, concurrent with CSR build.
    cudaEventRecord(evFork, 0);
    cudaStreamWaitEvent(s2, evFork, 0);
    gemm81_h<<<gemmGrid, gThr, 0, s2>>>(x, W1, (__half*)pH, N);

    // 1. CSR build + normalization (stream 0)
    hist_dst<<<(E + 255) / 256, 256>>>(ei, pCnt, E);
    scan1<<<nScanBlocks, SCAN_BLK>>>(pCnt, pRow, pBs, N);
    scan3<<<(N + 255) / 256, 256>>>(pRow, pCur, pBs, pCnt, pDis, N, nScanBlocks);
    cudaEventRecord(evDis, 0);            // dis ready
    // s2: scale rows by dis (overlaps with scatter on stream 0)
    cudaStreamWaitEvent(s2, evDis, 0);
    scale_dis<<<(total2 + 255) / 256, 256, 0, s2>>>(pH, pDis, total2);
    cudaEventRecord(evJoin, s2);
    // stream 0: scatter
    scatter_csr<<<(E + 255) / 256, 256>>>(ei, pCur, pCsr, E);
    cudaStreamWaitEvent(0, evJoin, 0);    // join before aggregate

    // 2. conv1 aggregate
    aggregate_h2<<<aggGrid, 256>>>(pH, pRow, pCsr, pDis, b1, (float4*)pB, N);

    // 3. BN1 raw stats
    bn_stats<<<512, 256>>>(pB, pStats1, N);

    // 4. conv2
    gemm64_bn_dis<<<gemmGrid, gThr>>>(pB, W2, pStats1, g1, be1, pDis, (__half*)pH, N);
    aggregate_h2<<<aggGrid, 256>>>(pH, pRow, pCsr, pDis, b2, (float4*)pA, N);

    // 5. BN2 raw stats
    bn_stats<<<512, 256>>>(pA, pStats2, N);

    // 6. Hs = relu(bn(A)) * dis ; shared aggregation for both heads
    bn_relu_dis<<<(NH + 255) / 256, 256>>>(pA, pStats2, g2, be2, pDis, (__half*)pH, NH, N);
    aggregate_h2<<<aggGrid, 256>>>(pH, pRow, pCsr, pDis, (const float*)nullptr, (float4*)pB, N);

    // 7. heads
    gemm_mu_ls<<<gemmGrid, gThr>>>(pB, Wmu, bmu, Wls, bls, out, N);
}